// round 5
// baseline (speedup 1.0000x reference)
#include <cuda_runtime.h>
#include <math_constants.h>

// ---------------------------------------------------------------------------
// ResonanceFidelityLoss — R5
// R3 two-kernel structure (R4 fusion regressed; reverted) + software-pipelined
// CE mainloop: prefetch next 4x float4 batch before processing current one
// (per-warp MLP 4 -> 8, targets DRAM% 84.8 -> ~90).
// ---------------------------------------------------------------------------

#define B 16
#define S 512
#define V 32000
#define NROWS (B * S)          // 8192
#define V4 (V / 4)             // 8000
#define CE_THREADS 256
#define BATCH (CE_THREADS * 4) // 1024 float4 per batched iter
#define MAIN_END ((V4 / BATCH) * BATCH)   // 7168

__device__ float g_nll[NROWS];
__device__ float g_res, g_att, g_har;

__device__ __forceinline__ float max4(float4 v) {
    return fmaxf(fmaxf(v.x, v.y), fmaxf(v.z, v.w));
}
__device__ __forceinline__ float esum4(float4 v, float m) {
    return __expf(v.x - m) + __expf(v.y - m)
         + __expf(v.z - m) + __expf(v.w - m);
}

// --- tiny dynamical system (MUFU sqrt/rcp; hidden block) --------------------
__device__ __forceinline__ void evolve4(float x[4]) {
    const float C[4][4] = {{1.0f, 1.4f, 1.3f, 1.5f},
                           {0.9f, 1.0f, 0.7f, 1.2f},
                           {0.6f, 0.8f, 1.0f, 0.5f},
                           {1.3f, 1.1f, 1.0f, 1.0f}};
    #pragma unroll 1
    for (int c = 0; c < 50; c++) {
        float d0 = x[0] - 1.0f, d1 = x[1] - 1.0f,
              d2 = x[2] - 1.0f, d3 = x[3] - 1.0f;
        float dist = __fsqrt_rn(d0*d0 + d1*d1 + d2*d2 + d3*d3);
        float kappa = 0.5f + __frcp_rn(1.0f + dist);
        float y[4];
        #pragma unroll
        for (int j = 0; j < 4; j++)
            y[j] = x[0]*C[0][j] + x[1]*C[1][j] + x[2]*C[2][j] + x[3]*C[3][j];
        #pragma unroll
        for (int j = 0; j < 4; j++) {
            float nx = x[j] + 0.1f * kappa * (y[j] - x[j]);
            x[j] = fminf(fmaxf(nx, 0.0f), 1.0f);
        }
    }
}

__device__ __forceinline__ float dist4(const float x[4]) {
    float d0 = x[0] - 1.0f, d1 = x[1] - 1.0f,
          d2 = x[2] - 1.0f, d3 = x[3] - 1.0f;
    return __fsqrt_rn(d0*d0 + d1*d1 + d2*d2 + d3*d3);
}

// --- CE rows + one hidden evolution block ----------------------------------
__global__ __launch_bounds__(CE_THREADS) void ce_kernel(
    const float* __restrict__ logits,
    const void*  __restrict__ targets,
    const float* __restrict__ src0,
    const float* __restrict__ tgt0)
{
    const int tid = threadIdx.x;

    if (blockIdx.x == NROWS) {
        // --- evolution block: lanes 0-15 = src rows, 16-31 = tgt rows ------
        if (tid < 32) {
            int b = tid & 15;
            const float* p = (tid < 16) ? (src0 + b * 4) : (tgt0 + b * 4);
            float x[4];
            #pragma unroll
            for (int j = 0; j < 4; j++) x[j] = p[j];
            evolve4(x);

            float d = dist4(x);
            float h = __frcp_rn(1.0f + d);

            float px0 = __shfl_xor_sync(0xFFFFFFFFu, x[0], 16);
            float px1 = __shfl_xor_sync(0xFFFFFFFFu, x[1], 16);
            float px2 = __shfl_xor_sync(0xFFFFFFFFu, x[2], 16);
            float px3 = __shfl_xor_sync(0xFFFFFFFFu, x[3], 16);
            float ph  = __shfl_xor_sync(0xFFFFFFFFu, h, 16);
            float pd  = __shfl_xor_sync(0xFFFFFFFFu, d, 16);

            float r0 = x[0]-px0, r1 = x[1]-px1, r2 = x[2]-px2, r3 = x[3]-px3;
            float res = __fsqrt_rn(r0*r0 + r1*r1 + r2*r2 + r3*r3);
            float att = 0.5f * (d + pd);
            float har = fabsf(h - ph);

            #pragma unroll
            for (int o = 8; o > 0; o >>= 1) {
                res += __shfl_down_sync(0xFFFFFFFFu, res, o);
                att += __shfl_down_sync(0xFFFFFFFFu, att, o);
                har += __shfl_down_sync(0xFFFFFFFFu, har, o);
            }
            if (tid == 0) {
                g_res = res * (1.0f / B);
                g_att = att * (1.0f / B);
                g_har = har * (1.0f / B);
            }
        }
        return;
    }

    const int row = blockIdx.x;
    const float4* __restrict__ rp =
        (const float4*)(logits + (size_t)row * V);

    float m = -CUDART_INF_F;
    float s = 0.0f;

    // software pipeline: batch i+1's 4 LDG.128 issue before batch i's exps
    float4 v0 = rp[tid];
    float4 v1 = rp[tid + CE_THREADS];
    float4 v2 = rp[tid + 2 * CE_THREADS];
    float4 v3 = rp[tid + 3 * CE_THREADS];

    #pragma unroll 1
    for (int base = BATCH; base < MAIN_END; base += BATCH) {
        float4 n0 = rp[base + tid];
        float4 n1 = rp[base + tid + CE_THREADS];
        float4 n2 = rp[base + tid + 2 * CE_THREADS];
        float4 n3 = rp[base + tid + 3 * CE_THREADS];

        float gm = fmaxf(fmaxf(max4(v0), max4(v1)),
                         fmaxf(max4(v2), max4(v3)));
        if (gm > m) {                  // rare after first iter
            s *= __expf(m - gm);       // first iter: 0 * exp(-inf) = 0
            m = gm;
        }
        s += esum4(v0, m) + esum4(v1, m) + esum4(v2, m) + esum4(v3, m);

        v0 = n0; v1 = n1; v2 = n2; v3 = n3;
    }
    // drain last pipelined batch
    {
        float gm = fmaxf(fmaxf(max4(v0), max4(v1)),
                         fmaxf(max4(v2), max4(v3)));
        if (gm > m) { s *= __expf(m - gm); m = gm; }
        s += esum4(v0, m) + esum4(v1, m) + esum4(v2, m) + esum4(v3, m);
    }
    // tail: 8000 - 7168 = 832 float4
    for (int i = MAIN_END + tid; i < V4; i += CE_THREADS) {
        float4 v = rp[i];
        float gm = max4(v);
        if (gm > m) { s *= __expf(m - gm); m = gm; }
        s += esum4(v, m);
    }

    // warp reduce (max, scaled-sum)
    #pragma unroll
    for (int o = 16; o > 0; o >>= 1) {
        float mo = __shfl_down_sync(0xFFFFFFFFu, m, o);
        float so = __shfl_down_sync(0xFFFFFFFFu, s, o);
        float mn = fmaxf(m, mo);
        s = s * __expf(m - mn) + so * __expf(mo - mn);
        m = mn;
    }

    __shared__ float wm[CE_THREADS / 32];
    __shared__ float ws[CE_THREADS / 32];
    const int warp = tid >> 5;
    const int lane = tid & 31;
    if (lane == 0) { wm[warp] = m; ws[warp] = s; }
    __syncthreads();

    if (tid == 0) {
        float M = wm[0], Ss = ws[0];
        #pragma unroll
        for (int w = 1; w < CE_THREADS / 32; w++) {
            float mo = wm[w], so = ws[w];
            float mn = fmaxf(M, mo);
            Ss = Ss * __expf(M - mn) + so * __expf(mo - mn);
            M = mn;
        }
        // int64 vs int32 detection (JAX x64-disabled ambiguity); 16 int64
        // probes all in [0,V) => true int64. L2-hit after first wave.
        const long long* __restrict__ t64 = (const long long*)targets;
        bool is64 = true;
        #pragma unroll
        for (int i = 0; i < 16; i++) {
            long long v = t64[i];
            if (v < 0 || v >= V) is64 = false;
        }
        long long t = is64 ? t64[row]
                           : (long long)((const int*)targets)[row];
        float lt = __ldg(logits + (size_t)row * V + t);
        g_nll[row] = M + __logf(Ss) - lt;
    }
}

// --- lean deterministic reduction + combine ---------------------------------
__global__ __launch_bounds__(1024) void finalize_kernel(float* __restrict__ out)
{
    const int tid = threadIdx.x;
    const float4* __restrict__ np = (const float4*)g_nll;   // 2048 float4

    float4 a = np[tid];
    float4 b = np[tid + 1024];
    float v = (a.x + a.y) + (a.z + a.w) + (b.x + b.y) + (b.z + b.w);

    #pragma unroll
    for (int o = 16; o > 0; o >>= 1)
        v += __shfl_down_sync(0xFFFFFFFFu, v, o);

    __shared__ float wsum[32];
    if ((tid & 31) == 0) wsum[tid >> 5] = v;
    __syncthreads();

    if (tid < 32) {
        float t = wsum[tid];
        #pragma unroll
        for (int o = 16; o > 0; o >>= 1)
            t += __shfl_down_sync(0xFFFFFFFFu, t, o);
        if (tid == 0) {
            float ce = t * (1.0f / NROWS);
            out[0] = 0.15f * ce + 0.5f * g_res + 0.2f * g_att + 0.15f * g_har;
        }
    }
}

extern "C" void kernel_launch(void* const* d_in, const int* in_sizes, int n_in,
                              void* d_out, int out_size)
{
    const float* logits  = (const float*)d_in[0];
    const void*  targets = d_in[1];
    const float* src     = (const float*)d_in[2];
    const float* tgt     = (const float*)d_in[3];
    float* out = (float*)d_out;

    ce_kernel<<<NROWS + 1, CE_THREADS>>>(logits, targets, src, tgt);
    finalize_kernel<<<1, 1024>>>(out);
}

// round 6
// speedup vs baseline: 1.0406x; 1.0406x over previous
#include <cuda_runtime.h>
#include <math_constants.h>

// ---------------------------------------------------------------------------
// ResonanceFidelityLoss — R6
// Exact R3 mainloop (best: 152.1us; R4 fusion and R5 pipelining both
// regressed — CE is pinned at the ~6.7TB/s LTS chip cap). New in R6:
// finalize launched via PDL (programmatic dependent launch) so its launch
// latency overlaps the CE grid's tail instead of serializing after it.
// ---------------------------------------------------------------------------

#define B 16
#define S 512
#define V 32000
#define NROWS (B * S)          // 8192
#define V4 (V / 4)             // 8000
#define CE_THREADS 256
#define BATCH (CE_THREADS * 4) // 1024 float4 per batched iter
#define MAIN_END ((V4 / BATCH) * BATCH)   // 7168

__device__ float g_nll[NROWS];
__device__ float g_res, g_att, g_har;

__device__ __forceinline__ float max4(float4 v) {
    return fmaxf(fmaxf(v.x, v.y), fmaxf(v.z, v.w));
}
__device__ __forceinline__ float esum4(float4 v, float m) {
    return __expf(v.x - m) + __expf(v.y - m)
         + __expf(v.z - m) + __expf(v.w - m);
}

// --- tiny dynamical system (MUFU sqrt/rcp; hidden block) --------------------
__device__ __forceinline__ void evolve4(float x[4]) {
    const float C[4][4] = {{1.0f, 1.4f, 1.3f, 1.5f},
                           {0.9f, 1.0f, 0.7f, 1.2f},
                           {0.6f, 0.8f, 1.0f, 0.5f},
                           {1.3f, 1.1f, 1.0f, 1.0f}};
    #pragma unroll 1
    for (int c = 0; c < 50; c++) {
        float d0 = x[0] - 1.0f, d1 = x[1] - 1.0f,
              d2 = x[2] - 1.0f, d3 = x[3] - 1.0f;
        float dist = __fsqrt_rn(d0*d0 + d1*d1 + d2*d2 + d3*d3);
        float kappa = 0.5f + __frcp_rn(1.0f + dist);
        float y[4];
        #pragma unroll
        for (int j = 0; j < 4; j++)
            y[j] = x[0]*C[0][j] + x[1]*C[1][j] + x[2]*C[2][j] + x[3]*C[3][j];
        #pragma unroll
        for (int j = 0; j < 4; j++) {
            float nx = x[j] + 0.1f * kappa * (y[j] - x[j]);
            x[j] = fminf(fmaxf(nx, 0.0f), 1.0f);
        }
    }
}

__device__ __forceinline__ float dist4(const float x[4]) {
    float d0 = x[0] - 1.0f, d1 = x[1] - 1.0f,
          d2 = x[2] - 1.0f, d3 = x[3] - 1.0f;
    return __fsqrt_rn(d0*d0 + d1*d1 + d2*d2 + d3*d3);
}

// --- CE rows + one hidden evolution block ----------------------------------
__global__ __launch_bounds__(CE_THREADS) void ce_kernel(
    const float* __restrict__ logits,
    const void*  __restrict__ targets,
    const float* __restrict__ src0,
    const float* __restrict__ tgt0)
{
    const int tid = threadIdx.x;

    if (blockIdx.x == NROWS) {
        // --- evolution block: lanes 0-15 = src rows, 16-31 = tgt rows ------
        if (tid < 32) {
            int b = tid & 15;
            const float* p = (tid < 16) ? (src0 + b * 4) : (tgt0 + b * 4);
            float x[4];
            #pragma unroll
            for (int j = 0; j < 4; j++) x[j] = p[j];
            evolve4(x);

            float d = dist4(x);
            float h = __frcp_rn(1.0f + d);

            float px0 = __shfl_xor_sync(0xFFFFFFFFu, x[0], 16);
            float px1 = __shfl_xor_sync(0xFFFFFFFFu, x[1], 16);
            float px2 = __shfl_xor_sync(0xFFFFFFFFu, x[2], 16);
            float px3 = __shfl_xor_sync(0xFFFFFFFFu, x[3], 16);
            float ph  = __shfl_xor_sync(0xFFFFFFFFu, h, 16);
            float pd  = __shfl_xor_sync(0xFFFFFFFFu, d, 16);

            float r0 = x[0]-px0, r1 = x[1]-px1, r2 = x[2]-px2, r3 = x[3]-px3;
            float res = __fsqrt_rn(r0*r0 + r1*r1 + r2*r2 + r3*r3);
            float att = 0.5f * (d + pd);
            float har = fabsf(h - ph);

            #pragma unroll
            for (int o = 8; o > 0; o >>= 1) {
                res += __shfl_down_sync(0xFFFFFFFFu, res, o);
                att += __shfl_down_sync(0xFFFFFFFFu, att, o);
                har += __shfl_down_sync(0xFFFFFFFFu, har, o);
            }
            if (tid == 0) {
                g_res = res * (1.0f / B);
                g_att = att * (1.0f / B);
                g_har = har * (1.0f / B);
            }
        }
        cudaTriggerProgrammaticLaunchCompletion();
        return;
    }

    const int row = blockIdx.x;
    const float4* __restrict__ rp =
        (const float4*)(logits + (size_t)row * V);

    float m = -CUDART_INF_F;
    float s = 0.0f;

    // main: 4 LDG.128 in flight before any MUFU consumes them (R3 form)
    #pragma unroll 1
    for (int base = 0; base < MAIN_END; base += BATCH) {
        float4 v0 = rp[base + tid];
        float4 v1 = rp[base + tid + CE_THREADS];
        float4 v2 = rp[base + tid + 2 * CE_THREADS];
        float4 v3 = rp[base + tid + 3 * CE_THREADS];
        float gm = fmaxf(fmaxf(max4(v0), max4(v1)),
                         fmaxf(max4(v2), max4(v3)));
        if (gm > m) {                  // rare after first iter
            s *= __expf(m - gm);       // first iter: 0 * exp(-inf) = 0
            m = gm;
        }
        s += esum4(v0, m) + esum4(v1, m) + esum4(v2, m) + esum4(v3, m);
    }
    // tail: 8000 - 7168 = 832 float4
    for (int i = MAIN_END + tid; i < V4; i += CE_THREADS) {
        float4 v = rp[i];
        float gm = max4(v);
        if (gm > m) { s *= __expf(m - gm); m = gm; }
        s += esum4(v, m);
    }

    // warp reduce (max, scaled-sum)
    #pragma unroll
    for (int o = 16; o > 0; o >>= 1) {
        float mo = __shfl_down_sync(0xFFFFFFFFu, m, o);
        float so = __shfl_down_sync(0xFFFFFFFFu, s, o);
        float mn = fmaxf(m, mo);
        s = s * __expf(m - mn) + so * __expf(mo - mn);
        m = mn;
    }

    __shared__ float wm[CE_THREADS / 32];
    __shared__ float ws[CE_THREADS / 32];
    const int warp = tid >> 5;
    const int lane = tid & 31;
    if (lane == 0) { wm[warp] = m; ws[warp] = s; }
    __syncthreads();

    if (tid == 0) {
        float M = wm[0], Ss = ws[0];
        #pragma unroll
        for (int w = 1; w < CE_THREADS / 32; w++) {
            float mo = wm[w], so = ws[w];
            float mn = fmaxf(M, mo);
            Ss = Ss * __expf(M - mn) + so * __expf(mo - mn);
            M = mn;
        }
        // int64 vs int32 detection (JAX x64-disabled ambiguity); 16 int64
        // probes all in [0,V) => true int64. L2-hit after first wave.
        const long long* __restrict__ t64 = (const long long*)targets;
        bool is64 = true;
        #pragma unroll
        for (int i = 0; i < 16; i++) {
            long long v = t64[i];
            if (v < 0 || v >= V) is64 = false;
        }
        long long t = is64 ? t64[row]
                           : (long long)((const int*)targets)[row];
        float lt = __ldg(logits + (size_t)row * V + t);
        g_nll[row] = M + __logf(Ss) - lt;
    }
    cudaTriggerProgrammaticLaunchCompletion();
}

// --- PDL finalize: spins up during CE tail, syncs, then reduces --------------
__global__ __launch_bounds__(1024) void finalize_kernel(float* __restrict__ out)
{
    const int tid = threadIdx.x;

    // Wait for ce_kernel's memory to be visible (PDL dependency sync).
    cudaGridDependencySynchronize();

    const float4* __restrict__ np = (const float4*)g_nll;   // 2048 float4

    float4 a = np[tid];
    float4 b = np[tid + 1024];
    float v = (a.x + a.y) + (a.z + a.w) + (b.x + b.y) + (b.z + b.w);

    #pragma unroll
    for (int o = 16; o > 0; o >>= 1)
        v += __shfl_down_sync(0xFFFFFFFFu, v, o);

    __shared__ float wsum[32];
    if ((tid & 31) == 0) wsum[tid >> 5] = v;
    __syncthreads();

    if (tid < 32) {
        float t = wsum[tid];
        #pragma unroll
        for (int o = 16; o > 0; o >>= 1)
            t += __shfl_down_sync(0xFFFFFFFFu, t, o);
        if (tid == 0) {
            float ce = t * (1.0f / NROWS);
            out[0] = 0.15f * ce + 0.5f * g_res + 0.2f * g_att + 0.15f * g_har;
        }
    }
}

extern "C" void kernel_launch(void* const* d_in, const int* in_sizes, int n_in,
                              void* d_out, int out_size)
{
    const float* logits  = (const float*)d_in[0];
    const void*  targets = d_in[1];
    const float* src     = (const float*)d_in[2];
    const float* tgt     = (const float*)d_in[3];
    float* out = (float*)d_out;

    ce_kernel<<<NROWS + 1, CE_THREADS>>>(logits, targets, src, tgt);

    // PDL launch: finalize overlaps ce_kernel's tail, then grid-dep-syncs.
    cudaLaunchConfig_t cfg = {};
    cfg.gridDim  = dim3(1, 1, 1);
    cfg.blockDim = dim3(1024, 1, 1);
    cfg.dynamicSmemBytes = 0;
    cfg.stream = 0;
    cudaLaunchAttribute attr[1];
    attr[0].id = cudaLaunchAttributeProgrammaticStreamSerialization;
    attr[0].val.programmaticStreamSerializationAllowed = 1;
    cfg.attrs = attr;
    cfg.numAttrs = 1;
    cudaLaunchKernelEx(&cfg, finalize_kernel, out);
}

// round 7
// speedup vs baseline: 1.0452x; 1.0044x over previous
#include <cuda_runtime.h>
#include <math_constants.h>

// ---------------------------------------------------------------------------
// ResonanceFidelityLoss — R7
// R6 structure (champion at 152.0us): R3 mainloop + PDL finalize.
// Single change: logits stream loads use __ldcs (evict-first, LDG.E.CS) —
// 1.048GB read-once data shouldn't allocate in L2. Everything else frozen.
// ---------------------------------------------------------------------------

#define B 16
#define S 512
#define V 32000
#define NROWS (B * S)          // 8192
#define V4 (V / 4)             // 8000
#define CE_THREADS 256
#define BATCH (CE_THREADS * 4) // 1024 float4 per batched iter
#define MAIN_END ((V4 / BATCH) * BATCH)   // 7168

__device__ float g_nll[NROWS];
__device__ float g_res, g_att, g_har;

__device__ __forceinline__ float max4(float4 v) {
    return fmaxf(fmaxf(v.x, v.y), fmaxf(v.z, v.w));
}
__device__ __forceinline__ float esum4(float4 v, float m) {
    return __expf(v.x - m) + __expf(v.y - m)
         + __expf(v.z - m) + __expf(v.w - m);
}

// --- tiny dynamical system (MUFU sqrt/rcp; hidden block) --------------------
__device__ __forceinline__ void evolve4(float x[4]) {
    const float C[4][4] = {{1.0f, 1.4f, 1.3f, 1.5f},
                           {0.9f, 1.0f, 0.7f, 1.2f},
                           {0.6f, 0.8f, 1.0f, 0.5f},
                           {1.3f, 1.1f, 1.0f, 1.0f}};
    #pragma unroll 1
    for (int c = 0; c < 50; c++) {
        float d0 = x[0] - 1.0f, d1 = x[1] - 1.0f,
              d2 = x[2] - 1.0f, d3 = x[3] - 1.0f;
        float dist = __fsqrt_rn(d0*d0 + d1*d1 + d2*d2 + d3*d3);
        float kappa = 0.5f + __frcp_rn(1.0f + dist);
        float y[4];
        #pragma unroll
        for (int j = 0; j < 4; j++)
            y[j] = x[0]*C[0][j] + x[1]*C[1][j] + x[2]*C[2][j] + x[3]*C[3][j];
        #pragma unroll
        for (int j = 0; j < 4; j++) {
            float nx = x[j] + 0.1f * kappa * (y[j] - x[j]);
            x[j] = fminf(fmaxf(nx, 0.0f), 1.0f);
        }
    }
}

__device__ __forceinline__ float dist4(const float x[4]) {
    float d0 = x[0] - 1.0f, d1 = x[1] - 1.0f,
          d2 = x[2] - 1.0f, d3 = x[3] - 1.0f;
    return __fsqrt_rn(d0*d0 + d1*d1 + d2*d2 + d3*d3);
}

// --- CE rows + one hidden evolution block ----------------------------------
__global__ __launch_bounds__(CE_THREADS) void ce_kernel(
    const float* __restrict__ logits,
    const void*  __restrict__ targets,
    const float* __restrict__ src0,
    const float* __restrict__ tgt0)
{
    const int tid = threadIdx.x;

    if (blockIdx.x == NROWS) {
        // --- evolution block: lanes 0-15 = src rows, 16-31 = tgt rows ------
        if (tid < 32) {
            int b = tid & 15;
            const float* p = (tid < 16) ? (src0 + b * 4) : (tgt0 + b * 4);
            float x[4];
            #pragma unroll
            for (int j = 0; j < 4; j++) x[j] = p[j];
            evolve4(x);

            float d = dist4(x);
            float h = __frcp_rn(1.0f + d);

            float px0 = __shfl_xor_sync(0xFFFFFFFFu, x[0], 16);
            float px1 = __shfl_xor_sync(0xFFFFFFFFu, x[1], 16);
            float px2 = __shfl_xor_sync(0xFFFFFFFFu, x[2], 16);
            float px3 = __shfl_xor_sync(0xFFFFFFFFu, x[3], 16);
            float ph  = __shfl_xor_sync(0xFFFFFFFFu, h, 16);
            float pd  = __shfl_xor_sync(0xFFFFFFFFu, d, 16);

            float r0 = x[0]-px0, r1 = x[1]-px1, r2 = x[2]-px2, r3 = x[3]-px3;
            float res = __fsqrt_rn(r0*r0 + r1*r1 + r2*r2 + r3*r3);
            float att = 0.5f * (d + pd);
            float har = fabsf(h - ph);

            #pragma unroll
            for (int o = 8; o > 0; o >>= 1) {
                res += __shfl_down_sync(0xFFFFFFFFu, res, o);
                att += __shfl_down_sync(0xFFFFFFFFu, att, o);
                har += __shfl_down_sync(0xFFFFFFFFu, har, o);
            }
            if (tid == 0) {
                g_res = res * (1.0f / B);
                g_att = att * (1.0f / B);
                g_har = har * (1.0f / B);
            }
        }
        cudaTriggerProgrammaticLaunchCompletion();
        return;
    }

    const int row = blockIdx.x;
    const float4* __restrict__ rp =
        (const float4*)(logits + (size_t)row * V);

    float m = -CUDART_INF_F;
    float s = 0.0f;

    // main: 4 LDG.128.CS in flight before any MUFU consumes them
    #pragma unroll 1
    for (int base = 0; base < MAIN_END; base += BATCH) {
        float4 v0 = __ldcs(rp + base + tid);
        float4 v1 = __ldcs(rp + base + tid + CE_THREADS);
        float4 v2 = __ldcs(rp + base + tid + 2 * CE_THREADS);
        float4 v3 = __ldcs(rp + base + tid + 3 * CE_THREADS);
        float gm = fmaxf(fmaxf(max4(v0), max4(v1)),
                         fmaxf(max4(v2), max4(v3)));
        if (gm > m) {                  // rare after first iter
            s *= __expf(m - gm);       // first iter: 0 * exp(-inf) = 0
            m = gm;
        }
        s += esum4(v0, m) + esum4(v1, m) + esum4(v2, m) + esum4(v3, m);
    }
    // tail: 8000 - 7168 = 832 float4
    for (int i = MAIN_END + tid; i < V4; i += CE_THREADS) {
        float4 v = __ldcs(rp + i);
        float gm = max4(v);
        if (gm > m) { s *= __expf(m - gm); m = gm; }
        s += esum4(v, m);
    }

    // warp reduce (max, scaled-sum)
    #pragma unroll
    for (int o = 16; o > 0; o >>= 1) {
        float mo = __shfl_down_sync(0xFFFFFFFFu, m, o);
        float so = __shfl_down_sync(0xFFFFFFFFu, s, o);
        float mn = fmaxf(m, mo);
        s = s * __expf(m - mn) + so * __expf(mo - mn);
        m = mn;
    }

    __shared__ float wm[CE_THREADS / 32];
    __shared__ float ws[CE_THREADS / 32];
    const int warp = tid >> 5;
    const int lane = tid & 31;
    if (lane == 0) { wm[warp] = m; ws[warp] = s; }
    __syncthreads();

    if (tid == 0) {
        float M = wm[0], Ss = ws[0];
        #pragma unroll
        for (int w = 1; w < CE_THREADS / 32; w++) {
            float mo = wm[w], so = ws[w];
            float mn = fmaxf(M, mo);
            Ss = Ss * __expf(M - mn) + so * __expf(mo - mn);
            M = mn;
        }
        // int64 vs int32 detection (JAX x64-disabled ambiguity); 16 int64
        // probes all in [0,V) => true int64. L2-hit after first wave.
        const long long* __restrict__ t64 = (const long long*)targets;
        bool is64 = true;
        #pragma unroll
        for (int i = 0; i < 16; i++) {
            long long v = t64[i];
            if (v < 0 || v >= V) is64 = false;
        }
        long long t = is64 ? t64[row]
                           : (long long)((const int*)targets)[row];
        float lt = __ldg(logits + (size_t)row * V + t);
        g_nll[row] = M + __logf(Ss) - lt;
    }
    cudaTriggerProgrammaticLaunchCompletion();
}

// --- PDL finalize: spins up during CE tail, syncs, then reduces --------------
__global__ __launch_bounds__(1024) void finalize_kernel(float* __restrict__ out)
{
    const int tid = threadIdx.x;

    // Wait for ce_kernel's memory to be visible (PDL dependency sync).
    cudaGridDependencySynchronize();

    const float4* __restrict__ np = (const float4*)g_nll;   // 2048 float4

    float4 a = np[tid];
    float4 b = np[tid + 1024];
    float v = (a.x + a.y) + (a.z + a.w) + (b.x + b.y) + (b.z + b.w);

    #pragma unroll
    for (int o = 16; o > 0; o >>= 1)
        v += __shfl_down_sync(0xFFFFFFFFu, v, o);

    __shared__ float wsum[32];
    if ((tid & 31) == 0) wsum[tid >> 5] = v;
    __syncthreads();

    if (tid < 32) {
        float t = wsum[tid];
        #pragma unroll
        for (int o = 16; o > 0; o >>= 1)
            t += __shfl_down_sync(0xFFFFFFFFu, t, o);
        if (tid == 0) {
            float ce = t * (1.0f / NROWS);
            out[0] = 0.15f * ce + 0.5f * g_res + 0.2f * g_att + 0.15f * g_har;
        }
    }
}

extern "C" void kernel_launch(void* const* d_in, const int* in_sizes, int n_in,
                              void* d_out, int out_size)
{
    const float* logits  = (const float*)d_in[0];
    const void*  targets = d_in[1];
    const float* src     = (const float*)d_in[2];
    const float* tgt     = (const float*)d_in[3];
    float* out = (float*)d_out;

    ce_kernel<<<NROWS + 1, CE_THREADS>>>(logits, targets, src, tgt);

    // PDL launch: finalize overlaps ce_kernel's tail, then grid-dep-syncs.
    cudaLaunchConfig_t cfg = {};
    cfg.gridDim  = dim3(1, 1, 1);
    cfg.blockDim = dim3(1024, 1, 1);
    cfg.dynamicSmemBytes = 0;
    cfg.stream = 0;
    cudaLaunchAttribute attr[1];
    attr[0].id = cudaLaunchAttributeProgrammaticStreamSerialization;
    attr[0].val.programmaticStreamSerializationAllowed = 1;
    cfg.attrs = attr;
    cfg.numAttrs = 1;
    cudaLaunchKernelEx(&cfg, finalize_kernel, out);
}

// round 8
// speedup vs baseline: 1.0475x; 1.0021x over previous
#include <cuda_runtime.h>
#include <math_constants.h>

// ---------------------------------------------------------------------------
// ResonanceFidelityLoss — R8
// R7 champion (151.4us): R3 mainloop + __ldcs streaming + PDL finalize.
// Single change: per-block target detection + target-logit fetch hoisted to
// block start (thread 0 -> smem), removing the serial dependent-load tail
// from each block's epilogue. Mainloop frozen.
// ---------------------------------------------------------------------------

#define B 16
#define S 512
#define V 32000
#define NROWS (B * S)          // 8192
#define V4 (V / 4)             // 8000
#define CE_THREADS 256
#define BATCH (CE_THREADS * 4) // 1024 float4 per batched iter
#define MAIN_END ((V4 / BATCH) * BATCH)   // 7168

__device__ float g_nll[NROWS];
__device__ float g_res, g_att, g_har;

__device__ __forceinline__ float max4(float4 v) {
    return fmaxf(fmaxf(v.x, v.y), fmaxf(v.z, v.w));
}
__device__ __forceinline__ float esum4(float4 v, float m) {
    return __expf(v.x - m) + __expf(v.y - m)
         + __expf(v.z - m) + __expf(v.w - m);
}

// --- tiny dynamical system (MUFU sqrt/rcp; hidden block) --------------------
__device__ __forceinline__ void evolve4(float x[4]) {
    const float C[4][4] = {{1.0f, 1.4f, 1.3f, 1.5f},
                           {0.9f, 1.0f, 0.7f, 1.2f},
                           {0.6f, 0.8f, 1.0f, 0.5f},
                           {1.3f, 1.1f, 1.0f, 1.0f}};
    #pragma unroll 1
    for (int c = 0; c < 50; c++) {
        float d0 = x[0] - 1.0f, d1 = x[1] - 1.0f,
              d2 = x[2] - 1.0f, d3 = x[3] - 1.0f;
        float dist = __fsqrt_rn(d0*d0 + d1*d1 + d2*d2 + d3*d3);
        float kappa = 0.5f + __frcp_rn(1.0f + dist);
        float y[4];
        #pragma unroll
        for (int j = 0; j < 4; j++)
            y[j] = x[0]*C[0][j] + x[1]*C[1][j] + x[2]*C[2][j] + x[3]*C[3][j];
        #pragma unroll
        for (int j = 0; j < 4; j++) {
            float nx = x[j] + 0.1f * kappa * (y[j] - x[j]);
            x[j] = fminf(fmaxf(nx, 0.0f), 1.0f);
        }
    }
}

__device__ __forceinline__ float dist4(const float x[4]) {
    float d0 = x[0] - 1.0f, d1 = x[1] - 1.0f,
          d2 = x[2] - 1.0f, d3 = x[3] - 1.0f;
    return __fsqrt_rn(d0*d0 + d1*d1 + d2*d2 + d3*d3);
}

// --- CE rows + one hidden evolution block ----------------------------------
__global__ __launch_bounds__(CE_THREADS) void ce_kernel(
    const float* __restrict__ logits,
    const void*  __restrict__ targets,
    const float* __restrict__ src0,
    const float* __restrict__ tgt0)
{
    const int tid = threadIdx.x;

    if (blockIdx.x == NROWS) {
        // --- evolution block: lanes 0-15 = src rows, 16-31 = tgt rows ------
        if (tid < 32) {
            int b = tid & 15;
            const float* p = (tid < 16) ? (src0 + b * 4) : (tgt0 + b * 4);
            float x[4];
            #pragma unroll
            for (int j = 0; j < 4; j++) x[j] = p[j];
            evolve4(x);

            float d = dist4(x);
            float h = __frcp_rn(1.0f + d);

            float px0 = __shfl_xor_sync(0xFFFFFFFFu, x[0], 16);
            float px1 = __shfl_xor_sync(0xFFFFFFFFu, x[1], 16);
            float px2 = __shfl_xor_sync(0xFFFFFFFFu, x[2], 16);
            float px3 = __shfl_xor_sync(0xFFFFFFFFu, x[3], 16);
            float ph  = __shfl_xor_sync(0xFFFFFFFFu, h, 16);
            float pd  = __shfl_xor_sync(0xFFFFFFFFu, d, 16);

            float r0 = x[0]-px0, r1 = x[1]-px1, r2 = x[2]-px2, r3 = x[3]-px3;
            float res = __fsqrt_rn(r0*r0 + r1*r1 + r2*r2 + r3*r3);
            float att = 0.5f * (d + pd);
            float har = fabsf(h - ph);

            #pragma unroll
            for (int o = 8; o > 0; o >>= 1) {
                res += __shfl_down_sync(0xFFFFFFFFu, res, o);
                att += __shfl_down_sync(0xFFFFFFFFu, att, o);
                har += __shfl_down_sync(0xFFFFFFFFu, har, o);
            }
            if (tid == 0) {
                g_res = res * (1.0f / B);
                g_att = att * (1.0f / B);
                g_har = har * (1.0f / B);
            }
        }
        cudaTriggerProgrammaticLaunchCompletion();
        return;
    }

    const int row = blockIdx.x;
    const float4* __restrict__ rp =
        (const float4*)(logits + (size_t)row * V);

    __shared__ float s_lt;   // target logit, fetched up-front by thread 0

    if (tid == 0) {
        // int64 vs int32 detection (JAX x64-disabled ambiguity); 16 int64
        // probes all in [0,V) => true int64. L2-hit after first wave.
        const long long* __restrict__ t64 = (const long long*)targets;
        bool is64 = true;
        #pragma unroll
        for (int i = 0; i < 16; i++) {
            long long v = t64[i];
            if (v < 0 || v >= V) is64 = false;
        }
        long long t = is64 ? t64[row]
                           : (long long)((const int*)targets)[row];
        s_lt = __ldg(logits + (size_t)row * V + t);
    }

    float m = -CUDART_INF_F;
    float s = 0.0f;

    // main: 4 LDG.128.CS in flight before any MUFU consumes them
    #pragma unroll 1
    for (int base = 0; base < MAIN_END; base += BATCH) {
        float4 v0 = __ldcs(rp + base + tid);
        float4 v1 = __ldcs(rp + base + tid + CE_THREADS);
        float4 v2 = __ldcs(rp + base + tid + 2 * CE_THREADS);
        float4 v3 = __ldcs(rp + base + tid + 3 * CE_THREADS);
        float gm = fmaxf(fmaxf(max4(v0), max4(v1)),
                         fmaxf(max4(v2), max4(v3)));
        if (gm > m) {                  // rare after first iter
            s *= __expf(m - gm);       // first iter: 0 * exp(-inf) = 0
            m = gm;
        }
        s += esum4(v0, m) + esum4(v1, m) + esum4(v2, m) + esum4(v3, m);
    }
    // tail: 8000 - 7168 = 832 float4
    for (int i = MAIN_END + tid; i < V4; i += CE_THREADS) {
        float4 v = __ldcs(rp + i);
        float gm = max4(v);
        if (gm > m) { s *= __expf(m - gm); m = gm; }
        s += esum4(v, m);
    }

    // warp reduce (max, scaled-sum)
    #pragma unroll
    for (int o = 16; o > 0; o >>= 1) {
        float mo = __shfl_down_sync(0xFFFFFFFFu, m, o);
        float so = __shfl_down_sync(0xFFFFFFFFu, s, o);
        float mn = fmaxf(m, mo);
        s = s * __expf(m - mn) + so * __expf(mo - mn);
        m = mn;
    }

    __shared__ float wm[CE_THREADS / 32];
    __shared__ float ws[CE_THREADS / 32];
    const int warp = tid >> 5;
    const int lane = tid & 31;
    if (lane == 0) { wm[warp] = m; ws[warp] = s; }
    __syncthreads();

    if (tid == 0) {
        float M = wm[0], Ss = ws[0];
        #pragma unroll
        for (int w = 1; w < CE_THREADS / 32; w++) {
            float mo = wm[w], so = ws[w];
            float mn = fmaxf(M, mo);
            Ss = Ss * __expf(M - mn) + so * __expf(mo - mn);
            M = mn;
        }
        g_nll[row] = M + __logf(Ss) - s_lt;
    }
    cudaTriggerProgrammaticLaunchCompletion();
}

// --- PDL finalize: spins up during CE tail, syncs, then reduces --------------
__global__ __launch_bounds__(1024) void finalize_kernel(float* __restrict__ out)
{
    const int tid = threadIdx.x;

    // Wait for ce_kernel's memory to be visible (PDL dependency sync).
    cudaGridDependencySynchronize();

    const float4* __restrict__ np = (const float4*)g_nll;   // 2048 float4

    float4 a = np[tid];
    float4 b = np[tid + 1024];
    float v = (a.x + a.y) + (a.z + a.w) + (b.x + b.y) + (b.z + b.w);

    #pragma unroll
    for (int o = 16; o > 0; o >>= 1)
        v += __shfl_down_sync(0xFFFFFFFFu, v, o);

    __shared__ float wsum[32];
    if ((tid & 31) == 0) wsum[tid >> 5] = v;
    __syncthreads();

    if (tid < 32) {
        float t = wsum[tid];
        #pragma unroll
        for (int o = 16; o > 0; o >>= 1)
            t += __shfl_down_sync(0xFFFFFFFFu, t, o);
        if (tid == 0) {
            float ce = t * (1.0f / NROWS);
            out[0] = 0.15f * ce + 0.5f * g_res + 0.2f * g_att + 0.15f * g_har;
        }
    }
}

extern "C" void kernel_launch(void* const* d_in, const int* in_sizes, int n_in,
                              void* d_out, int out_size)
{
    const float* logits  = (const float*)d_in[0];
    const void*  targets = d_in[1];
    const float* src     = (const float*)d_in[2];
    const float* tgt     = (const float*)d_in[3];
    float* out = (float*)d_out;

    ce_kernel<<<NROWS + 1, CE_THREADS>>>(logits, targets, src, tgt);

    // PDL launch: finalize overlaps ce_kernel's tail, then grid-dep-syncs.
    cudaLaunchConfig_t cfg = {};
    cfg.gridDim  = dim3(1, 1, 1);
    cfg.blockDim = dim3(1024, 1, 1);
    cfg.dynamicSmemBytes = 0;
    cfg.stream = 0;
    cudaLaunchAttribute attr[1];
    attr[0].id = cudaLaunchAttributeProgrammaticStreamSerialization;
    attr[0].val.programmaticStreamSerializationAllowed = 1;
    cfg.attrs = attr;
    cfg.numAttrs = 1;
    cudaLaunchKernelEx(&cfg, finalize_kernel, out);
}